// round 11
// baseline (speedup 1.0000x reference)
#include <cuda_runtime.h>
#include <cstddef>

// JPEG 8x8 blockify + orthonormal 2D DCT-II + QF quantization.
// image: [16,1,1024,1024] f32, qf: [16] f32 -> out [16,64,128,128] f32.
//
// R11 = R8 math (2 threads/block, shuffle-pair row DCT, __ldcg/__stcs)
// with a CTA-wide smem-transpose store epilogue:
//   compute -> stage[plane][wb] (stride 132, conflict-free) -> __syncthreads
//   -> each warp writes 8 whole planes as STG.128, 512B contiguous per
//   warp-instruction. Fixes DRAM write locality (was: 64B crumbs scattered
//   across 32 planes per warp) and cuts store instructions 4x.

#define A0 0.35355339059327373f  // 1/sqrt(8)
#define H1 0.49039264020161522f  // cos(1*pi/16)/2
#define H2 0.46193976625564337f  // cos(2*pi/16)/2
#define H3 0.41573480615127262f  // cos(3*pi/16)/2
#define H4 0.35355339059327376f  // cos(4*pi/16)/2
#define H5 0.27778511650980111f  // cos(5*pi/16)/2
#define H6 0.19134171618254489f  // cos(6*pi/16)/2
#define H7 0.09754516100806413f  // cos(7*pi/16)/2

__constant__ float c_qtab[64] = {
    16.f, 11.f, 10.f, 16.f, 24.f, 40.f, 51.f, 61.f,
    12.f, 12.f, 14.f, 19.f, 26.f, 58.f, 60.f, 55.f,
    14.f, 13.f, 16.f, 24.f, 40.f, 57.f, 69.f, 56.f,
    14.f, 17.f, 22.f, 29.f, 51.f, 87.f, 80.f, 62.f,
    18.f, 22.f, 37.f, 56.f, 68.f, 109.f, 103.f, 77.f,
    24.f, 36.f, 55.f, 64.f, 81.f, 104.f, 113.f, 92.f,
    49.f, 64.f, 78.f, 87.f, 103.f, 121.f, 120.f, 101.f,
    72.f, 92.f, 95.f, 98.f, 112.f, 100.f, 103.f, 99.f};

#define PSTRIDE 132  // plane stride in words: +4 pad => STS halves and
                     // LDS.128 readout are bank-conflict-free

__device__ __forceinline__ void dct8(float& x0, float& x1, float& x2, float& x3,
                                     float& x4, float& x5, float& x6, float& x7) {
    float e0 = x0 + x7, e1 = x1 + x6, e2 = x2 + x5, e3 = x3 + x4;
    float o0 = x0 - x7, o1 = x1 - x6, o2 = x2 - x5, o3 = x3 - x4;
    float ee0 = e0 + e3, ee1 = e1 + e2;
    float eo0 = e0 - e3, eo1 = e1 - e2;
    x0 = A0 * (ee0 + ee1);
    x4 = H4 * (ee0 - ee1);
    x2 = H2 * eo0 + H6 * eo1;
    x6 = H6 * eo0 - H2 * eo1;
    x1 = H1 * o0 + H3 * o1 + H5 * o2 + H7 * o3;
    x3 = H3 * o0 - H7 * o1 - H1 * o2 - H5 * o3;
    x5 = H5 * o0 - H1 * o1 + H7 * o2 + H3 * o3;
    x7 = H7 * o0 - H5 * o1 + H3 * o2 - H1 * o3;
}

__global__ __launch_bounds__(256, 4) void jpeg_dct_kernel(
    const float* __restrict__ img,
    const float* __restrict__ qf,
    float* __restrict__ out) {
    __shared__ __align__(16) float sScale[64];
    __shared__ __align__(16) float stage[64 * PSTRIDE];  // 33.8 KB

    // CTA = one block-row: b = blockIdx>>7, hb = blockIdx&127, wb = tid>>1.
    int b = blockIdx.x >> 7;
    int hb = blockIdx.x & 127;
    int wb = threadIdx.x >> 1;
    int h = threadIdx.x & 1;   // half: columns 4h..4h+3
    bool hi = (h != 0);

    if (threadIdx.x < 64) {
        float q = qf[b];
        float factor = (q < 50.0f) ? (5000.0f / q) : (200.0f - 2.0f * q);
        sScale[threadIdx.x] = 100.0f / (c_qtab[threadIdx.x] * factor);
    }
    __syncthreads();

    // Loads: lane pair covers 32B; warp covers 512B contiguous per row.
    const float* p = img + ((size_t)b << 20) + (size_t)hb * 8192 + wb * 8 + h * 4;

    float x[8][4];
#pragma unroll
    for (int r = 0; r < 8; r++) {
        float4 v = __ldcg((const float4*)(p + (size_t)r * 1024));
        x[r][0] = v.x - 128.0f;
        x[r][1] = v.y - 128.0f;
        x[r][2] = v.z - 128.0f;
        x[r][3] = v.w - 128.0f;
    }

    // Column transform: thread-local, own 4 columns.
#pragma unroll
    for (int c = 0; c < 4; c++) {
        dct8(x[0][c], x[1][c], x[2][c], x[3][c],
             x[4][c], x[5][c], x[6][c], x[7][c]);
    }

    // Per-half row-transform coefficients (selected once):
    //   h=0 emits l = 0,1,2,3 ; h=1 emits l = 4,5,6,7
    float cA0 = hi ?  H4 :  A0, cA1 = hi ? -H4 :  A0;   // l0 / l4
    float cB0 = hi ? -H6 :  H2, cB1 = hi ?  H2 :  H6;   // l2 / l6
    float cC0 = hi ? -H3 :  H1, cC1 = hi ? -H7 :  H3,   // l1 / l5
          cC2 = hi ?  H1 :  H5, cC3 = hi ? -H5 :  H7;
    float cD0 = hi ?  H1 :  H3, cD1 = hi ? -H3 : -H7,   // l3 / l7
          cD2 = hi ?  H5 : -H1, cD3 = hi ? -H7 : -H5;

    // Staging base for this thread: plane = k*8 + 4h + j, word = plane*PSTRIDE + wb
    float* st = &stage[(4 * h) * PSTRIDE + wb];

#pragma unroll
    for (int k = 0; k < 8; k++) {
        float v0 = x[k][0], v1 = x[k][1], v2 = x[k][2], v3 = x[k][3];
        float p0 = __shfl_xor_sync(0xffffffffu, v0, 1);
        float p1 = __shfl_xor_sync(0xffffffffu, v1, 1);
        float p2 = __shfl_xor_sync(0xffffffffu, v2, 1);
        float p3 = __shfl_xor_sync(0xffffffffu, v3, 1);
        float s0 = v0 + p3, s1 = v1 + p2, s2 = v2 + p1, s3 = v3 + p0;
        float d0 = v0 - p3, d1 = v1 - p2, d2 = v2 - p1, d3 = v3 - p0;
        float ee0 = s0 + s3, ee1 = s1 + s2;
        float u0 = s0 - s3, u1 = s1 - s2;

        float oA = cA0 * ee0 + cA1 * ee1;                      // l = 4h+0
        float oB = cB0 * u0 + cB1 * u1;                        // l = 4h+2
        float oC = cC0 * d0 + cC1 * d1 + cC2 * d2 + cC3 * d3;  // l = 4h+1
        float oD = cD0 * d0 + cD1 * d1 + cD2 * d2 + cD3 * d3;  // l = 4h+3

        float4 sc = *(const float4*)&sScale[k * 8 + 4 * h];
        float* sk = st + (k * 8) * PSTRIDE;
        sk[0 * PSTRIDE] = oA * sc.x;
        sk[1 * PSTRIDE] = oC * sc.y;
        sk[2 * PSTRIDE] = oB * sc.z;
        sk[3 * PSTRIDE] = oD * sc.w;
    }

    __syncthreads();

    // Epilogue: warp w streams planes 8w..8w+7. One STG.128 per plane per
    // warp = 512B fully contiguous. Consecutive CTAs (consecutive hb)
    // extend each plane row contiguously in DRAM.
    int warp = threadIdx.x >> 5;
    int lane = threadIdx.x & 31;
    float* ob = out + ((size_t)b << 20) + hb * 128 + lane * 4;
#pragma unroll
    for (int it = 0; it < 8; it++) {
        int pl = warp * 8 + it;
        float4 v = *(const float4*)&stage[pl * PSTRIDE + lane * 4];
        __stcs((float4*)(ob + (size_t)pl * 16384), v);
    }
}

extern "C" void kernel_launch(void* const* d_in, const int* in_sizes, int n_in,
                              void* d_out, int out_size) {
    const float* img = (const float*)d_in[0];
    const float* qf = (const float*)d_in[1];
    float* out = (float*)d_out;
    // 2048 CTAs: one per (image, block-row)
    jpeg_dct_kernel<<<2048, 256>>>(img, qf, out);
}

// round 12
// speedup vs baseline: 1.3040x; 1.3040x over previous
#include <cuda_runtime.h>
#include <cstddef>

// JPEG 8x8 blockify + orthonormal 2D DCT-II + QF quantization.
// image: [16,1,1024,1024] f32, qf: [16] f32 -> out [16,64,128,128] f32.
//
// R12 = R8 body (2 threads per 8x8 block, shuffle-pair row DCT,
// __ldcg loads / __stcs stores — the only changes that ever won) made
// PERSISTENT: 592 CTAs (exactly 4/SM), each grid-striding over block-rows.
//   - kills the 46%-full tail wave of the 2048-CTA launch
//   - iteration i+1 loads are independent of iteration i stores, so the
//     scoreboard overlaps them -> continuous DRAM read stream
// All 16 images' quant scales precomputed once into 4KB smem (one barrier
// total, none inside the loop).

#define A0 0.35355339059327373f  // 1/sqrt(8)
#define H1 0.49039264020161522f  // cos(1*pi/16)/2
#define H2 0.46193976625564337f  // cos(2*pi/16)/2
#define H3 0.41573480615127262f  // cos(3*pi/16)/2
#define H4 0.35355339059327376f  // cos(4*pi/16)/2
#define H5 0.27778511650980111f  // cos(5*pi/16)/2
#define H6 0.19134171618254489f  // cos(6*pi/16)/2
#define H7 0.09754516100806413f  // cos(7*pi/16)/2

__constant__ float c_qtab[64] = {
    16.f, 11.f, 10.f, 16.f, 24.f, 40.f, 51.f, 61.f,
    12.f, 12.f, 14.f, 19.f, 26.f, 58.f, 60.f, 55.f,
    14.f, 13.f, 16.f, 24.f, 40.f, 57.f, 69.f, 56.f,
    14.f, 17.f, 22.f, 29.f, 51.f, 87.f, 80.f, 62.f,
    18.f, 22.f, 37.f, 56.f, 68.f, 109.f, 103.f, 77.f,
    24.f, 36.f, 55.f, 64.f, 81.f, 104.f, 113.f, 92.f,
    49.f, 64.f, 78.f, 87.f, 103.f, 121.f, 120.f, 101.f,
    72.f, 92.f, 95.f, 98.f, 112.f, 100.f, 103.f, 99.f};

#define NROWS 2048   // 16 images * 128 block-rows

__device__ __forceinline__ void dct8(float& x0, float& x1, float& x2, float& x3,
                                     float& x4, float& x5, float& x6, float& x7) {
    float e0 = x0 + x7, e1 = x1 + x6, e2 = x2 + x5, e3 = x3 + x4;
    float o0 = x0 - x7, o1 = x1 - x6, o2 = x2 - x5, o3 = x3 - x4;
    float ee0 = e0 + e3, ee1 = e1 + e2;
    float eo0 = e0 - e3, eo1 = e1 - e2;
    x0 = A0 * (ee0 + ee1);
    x4 = H4 * (ee0 - ee1);
    x2 = H2 * eo0 + H6 * eo1;
    x6 = H6 * eo0 - H2 * eo1;
    x1 = H1 * o0 + H3 * o1 + H5 * o2 + H7 * o3;
    x3 = H3 * o0 - H7 * o1 - H1 * o2 - H5 * o3;
    x5 = H5 * o0 - H1 * o1 + H7 * o2 + H3 * o3;
    x7 = H7 * o0 - H5 * o1 + H3 * o2 - H1 * o3;
}

__global__ __launch_bounds__(256, 4) void jpeg_dct_kernel(
    const float* __restrict__ img,
    const float* __restrict__ qf,
    float* __restrict__ out) {
    __shared__ __align__(16) float sScale[16 * 64];  // all images' scales

    // Precompute every image's 64 quant scales once.
    for (int i = threadIdx.x; i < 16 * 64; i += 256) {
        int bi = i >> 6;
        float q = qf[bi];
        float factor = (q < 50.0f) ? (5000.0f / q) : (200.0f - 2.0f * q);
        sScale[i] = 100.0f / (c_qtab[i & 63] * factor);
    }
    __syncthreads();

    int wb = threadIdx.x >> 1;
    int h = threadIdx.x & 1;   // half: columns 4h..4h+3
    bool hi = (h != 0);

    // Per-half row-transform coefficients (selected once):
    //   h=0 emits l = 0,1,2,3 ; h=1 emits l = 4,5,6,7
    float cA0 = hi ?  H4 :  A0, cA1 = hi ? -H4 :  A0;   // l0 / l4
    float cB0 = hi ? -H6 :  H2, cB1 = hi ?  H2 :  H6;   // l2 / l6
    float cC0 = hi ? -H3 :  H1, cC1 = hi ? -H7 :  H3,   // l1 / l5
          cC2 = hi ?  H1 :  H5, cC3 = hi ? -H5 :  H7;
    float cD0 = hi ?  H1 :  H3, cD1 = hi ? -H3 : -H7,   // l3 / l7
          cD2 = hi ?  H5 : -H1, cD3 = hi ? -H7 : -H5;

    // Persistent loop over block-rows. Consecutive CTAs -> consecutive hb.
    for (int row = blockIdx.x; row < NROWS; row += gridDim.x) {
        int b = row >> 7;
        int hb = row & 127;

        const float* p = img + ((size_t)b << 20) + (size_t)hb * 8192 + wb * 8 + h * 4;

        float x[8][4];
#pragma unroll
        for (int r = 0; r < 8; r++) {
            float4 v = __ldcg((const float4*)(p + (size_t)r * 1024));
            x[r][0] = v.x - 128.0f;
            x[r][1] = v.y - 128.0f;
            x[r][2] = v.z - 128.0f;
            x[r][3] = v.w - 128.0f;
        }

        // Column transform: thread-local, own 4 columns.
#pragma unroll
        for (int c = 0; c < 4; c++) {
            dct8(x[0][c], x[1][c], x[2][c], x[3][c],
                 x[4][c], x[5][c], x[6][c], x[7][c]);
        }

        const float* scb = &sScale[b * 64 + 4 * h];
        float* ob = out + ((size_t)b << 20) + hb * 128 + wb + (size_t)(h * 4) * 16384;

#pragma unroll
        for (int k = 0; k < 8; k++) {
            float v0 = x[k][0], v1 = x[k][1], v2 = x[k][2], v3 = x[k][3];
            float p0 = __shfl_xor_sync(0xffffffffu, v0, 1);
            float p1 = __shfl_xor_sync(0xffffffffu, v1, 1);
            float p2 = __shfl_xor_sync(0xffffffffu, v2, 1);
            float p3 = __shfl_xor_sync(0xffffffffu, v3, 1);
            // s_i = e_i (h=0) / e_{3-i} (h=1);  d_i = o_i (h=0) / -o_{3-i} (h=1)
            float s0 = v0 + p3, s1 = v1 + p2, s2 = v2 + p1, s3 = v3 + p0;
            float d0 = v0 - p3, d1 = v1 - p2, d2 = v2 - p1, d3 = v3 - p0;
            float ee0 = s0 + s3, ee1 = s1 + s2;
            float u0 = s0 - s3, u1 = s1 - s2;

            float oA = cA0 * ee0 + cA1 * ee1;                      // l = 4h+0
            float oB = cB0 * u0 + cB1 * u1;                        // l = 4h+2
            float oC = cC0 * d0 + cC1 * d1 + cC2 * d2 + cC3 * d3;  // l = 4h+1
            float oD = cD0 * d0 + cD1 * d1 + cD2 * d2 + cD3 * d3;  // l = 4h+3

            float4 sc = *(const float4*)&scb[k * 8];
            float* ok = ob + (size_t)(k * 8) * 16384;
            __stcs(ok,                     oA * sc.x);
            __stcs(ok + (size_t)1 * 16384, oC * sc.y);
            __stcs(ok + (size_t)2 * 16384, oB * sc.z);
            __stcs(ok + (size_t)3 * 16384, oD * sc.w);
        }
    }
}

extern "C" void kernel_launch(void* const* d_in, const int* in_sizes, int n_in,
                              void* d_out, int out_size) {
    const float* img = (const float*)d_in[0];
    const float* qf = (const float*)d_in[1];
    float* out = (float*)d_out;
    // 592 = 4 CTAs/SM * 148 SMs; persistent grid-stride over 2048 block-rows.
    jpeg_dct_kernel<<<592, 256>>>(img, qf, out);
}

// round 14
// speedup vs baseline: 1.3185x; 1.0111x over previous
#include <cuda_runtime.h>
#include <cstddef>

// JPEG 8x8 blockify + orthonormal 2D DCT-II + QF quantization.
// image: [16,1,1024,1024] f32, qf: [16] f32 -> out [16,64,128,128] f32.
//
// R14 = R8 (best e2e: 2 threads per 8x8 block, shuffle-pair row DCT,
// __stcs streaming stores) + L2 evict-last pinning of the input via the
// createpolicy/cache_hint form (the bare .L2::evict_last qualifier is
// rejected by ptxas for .v4.f32 loads on sm_103):
//   createpolicy.fractional.L2::evict_last.b64 pol, 1.0;
//   ld.global.nc.L2::cache_hint.v4.f32 {..}, [p], pol;
// Steady-state across graph replays: the 64MiB input persists in L2 as the
// high-priority set; the evict-first write stream passes through the rest.

#define A0 0.35355339059327373f  // 1/sqrt(8)
#define H1 0.49039264020161522f  // cos(1*pi/16)/2
#define H2 0.46193976625564337f  // cos(2*pi/16)/2
#define H3 0.41573480615127262f  // cos(3*pi/16)/2
#define H4 0.35355339059327376f  // cos(4*pi/16)/2
#define H5 0.27778511650980111f  // cos(5*pi/16)/2
#define H6 0.19134171618254489f  // cos(6*pi/16)/2
#define H7 0.09754516100806413f  // cos(7*pi/16)/2

__constant__ float c_qtab[64] = {
    16.f, 11.f, 10.f, 16.f, 24.f, 40.f, 51.f, 61.f,
    12.f, 12.f, 14.f, 19.f, 26.f, 58.f, 60.f, 55.f,
    14.f, 13.f, 16.f, 24.f, 40.f, 57.f, 69.f, 56.f,
    14.f, 17.f, 22.f, 29.f, 51.f, 87.f, 80.f, 62.f,
    18.f, 22.f, 37.f, 56.f, 68.f, 109.f, 103.f, 77.f,
    24.f, 36.f, 55.f, 64.f, 81.f, 104.f, 113.f, 92.f,
    49.f, 64.f, 78.f, 87.f, 103.f, 121.f, 120.f, 101.f,
    72.f, 92.f, 95.f, 98.f, 112.f, 100.f, 103.f, 99.f};

__device__ __forceinline__ unsigned long long mk_evict_last_policy() {
    unsigned long long pol;
    asm("createpolicy.fractional.L2::evict_last.b64 %0, 1.0;" : "=l"(pol));
    return pol;
}

__device__ __forceinline__ float4 ldg_hint(const float* __restrict__ p,
                                           unsigned long long pol) {
    float4 v;
    asm("ld.global.nc.L2::cache_hint.v4.f32 {%0,%1,%2,%3}, [%4], %5;"
        : "=f"(v.x), "=f"(v.y), "=f"(v.z), "=f"(v.w) : "l"(p), "l"(pol));
    return v;
}

__device__ __forceinline__ void dct8(float& x0, float& x1, float& x2, float& x3,
                                     float& x4, float& x5, float& x6, float& x7) {
    float e0 = x0 + x7, e1 = x1 + x6, e2 = x2 + x5, e3 = x3 + x4;
    float o0 = x0 - x7, o1 = x1 - x6, o2 = x2 - x5, o3 = x3 - x4;
    float ee0 = e0 + e3, ee1 = e1 + e2;
    float eo0 = e0 - e3, eo1 = e1 - e2;
    x0 = A0 * (ee0 + ee1);
    x4 = H4 * (ee0 - ee1);
    x2 = H2 * eo0 + H6 * eo1;
    x6 = H6 * eo0 - H2 * eo1;
    x1 = H1 * o0 + H3 * o1 + H5 * o2 + H7 * o3;
    x3 = H3 * o0 - H7 * o1 - H1 * o2 - H5 * o3;
    x5 = H5 * o0 - H1 * o1 + H7 * o2 + H3 * o3;
    x7 = H7 * o0 - H5 * o1 + H3 * o2 - H1 * o3;
}

__global__ __launch_bounds__(256, 4) void jpeg_dct_kernel(
    const float* __restrict__ img,
    const float* __restrict__ qf,
    float* __restrict__ out) {
    __shared__ __align__(16) float sScale[64];

    int tid = blockIdx.x * 256 + threadIdx.x;
    int b = tid >> 15;  // 2 threads/block, 32768 threads per image; CTA-uniform

    if (threadIdx.x < 64) {
        float q = qf[b];
        float factor = (q < 50.0f) ? (5000.0f / q) : (200.0f - 2.0f * q);
        sScale[threadIdx.x] = 100.0f / (c_qtab[threadIdx.x] * factor);
    }
    __syncthreads();

    int bid = tid >> 1;      // 8x8 block index
    int h = tid & 1;         // half: columns 4h..4h+3
    int hb = (bid >> 7) & 127;
    int wb = bid & 127;

    // Loads: lane pair covers 32B; warp covers 512B contiguous per row.
    const float* p = img + ((size_t)b << 20) + (size_t)hb * 8192 + wb * 8 + h * 4;
    unsigned long long pol = mk_evict_last_policy();

    float x[8][4];
#pragma unroll
    for (int r = 0; r < 8; r++) {
        float4 v = ldg_hint(p + (size_t)r * 1024, pol);
        x[r][0] = v.x - 128.0f;
        x[r][1] = v.y - 128.0f;
        x[r][2] = v.z - 128.0f;
        x[r][3] = v.w - 128.0f;
    }

    // Column transform: thread-local, 4 columns.
#pragma unroll
    for (int c = 0; c < 4; c++) {
        dct8(x[0][c], x[1][c], x[2][c], x[3][c],
             x[4][c], x[5][c], x[6][c], x[7][c]);
    }

    // Per-half row-transform coefficients (selected once; both halves then
    // execute the identical arithmetic on s/d):
    //   h=0 emits l = 0,1,2,3 ; h=1 emits l = 4,5,6,7
    bool hi = (h != 0);
    float cA0 = hi ?  H4 :  A0, cA1 = hi ? -H4 :  A0;   // l0 / l4
    float cB0 = hi ? -H6 :  H2, cB1 = hi ?  H2 :  H6;   // l2 / l6
    float cC0 = hi ? -H3 :  H1, cC1 = hi ? -H7 :  H3,   // l1 / l5
          cC2 = hi ?  H1 :  H5, cC3 = hi ? -H5 :  H7;
    float cD0 = hi ?  H1 :  H3, cD1 = hi ? -H3 : -H7,   // l3 / l7
          cD2 = hi ?  H5 : -H1, cD3 = hi ? -H7 : -H5;

    float* ob = out + ((size_t)b << 20) + hb * 128 + wb + (size_t)(h * 4) * 16384;

#pragma unroll
    for (int k = 0; k < 8; k++) {
        float v0 = x[k][0], v1 = x[k][1], v2 = x[k][2], v3 = x[k][3];
        float p0 = __shfl_xor_sync(0xffffffffu, v0, 1);
        float p1 = __shfl_xor_sync(0xffffffffu, v1, 1);
        float p2 = __shfl_xor_sync(0xffffffffu, v2, 1);
        float p3 = __shfl_xor_sync(0xffffffffu, v3, 1);
        // s_i = e_i (h=0) / e_{3-i} (h=1);  d_i = o_i (h=0) / -o_{3-i} (h=1)
        float s0 = v0 + p3, s1 = v1 + p2, s2 = v2 + p1, s3 = v3 + p0;
        float d0 = v0 - p3, d1 = v1 - p2, d2 = v2 - p1, d3 = v3 - p0;
        float ee0 = s0 + s3, ee1 = s1 + s2;
        float u0 = s0 - s3, u1 = s1 - s2;

        float oA = cA0 * ee0 + cA1 * ee1;                              // l = 4h+0
        float oB = cB0 * u0 + cB1 * u1;                                // l = 4h+2
        float oC = cC0 * d0 + cC1 * d1 + cC2 * d2 + cC3 * d3;          // l = 4h+1
        float oD = cD0 * d0 + cD1 * d1 + cD2 * d2 + cD3 * d3;          // l = 4h+3

        float4 sc = *(const float4*)&sScale[k * 8 + 4 * h];
        float* ok = ob + (size_t)(k * 8) * 16384;
        __stcs(ok,                     oA * sc.x);
        __stcs(ok + (size_t)1 * 16384, oC * sc.y);
        __stcs(ok + (size_t)2 * 16384, oB * sc.z);
        __stcs(ok + (size_t)3 * 16384, oD * sc.w);
    }
}

extern "C" void kernel_launch(void* const* d_in, const int* in_sizes, int n_in,
                              void* d_out, int out_size) {
    const float* img = (const float*)d_in[0];
    const float* qf = (const float*)d_in[1];
    float* out = (float*)d_out;
    // 16 images * 16384 blocks * 2 threads = 524288 threads -> 2048 CTAs
    jpeg_dct_kernel<<<2048, 256>>>(img, qf, out);
}

// round 15
// speedup vs baseline: 1.4385x; 1.0910x over previous
#include <cuda_runtime.h>
#include <cstddef>

// JPEG 8x8 blockify + orthonormal 2D DCT-II + QF quantization.
// image: [16,1,1024,1024] f32, qf: [16] f32 -> out [16,64,128,128] f32.
//
// R15 = R14 body (2 threads per 8x8 block, shuffle-pair row DCT,
// evict-last L2-pinned loads, __stcs streaming stores) restructured as a
// PERSISTENT kernel with REGISTER double-buffered software pipelining:
// each CTA grid-strides over block-rows, issuing iteration i+1's 8 LDG.128
// before computing iteration i, so loads are in flight during the entire
// compute+store phase (fixes the ~50% DRAM read duty cycle seen in every
// profile). Two register tiles (ping-pong, no copies), ~100 regs,
// __launch_bounds__(256,2), grid=296 (2 CTAs/SM).
// Also folds the -128 input shift into a single DC fix (only out[0][0]
// is affected, by -1024), removing 32 FADDs per thread.

#define A0 0.35355339059327373f  // 1/sqrt(8)
#define H1 0.49039264020161522f  // cos(1*pi/16)/2
#define H2 0.46193976625564337f  // cos(2*pi/16)/2
#define H3 0.41573480615127262f  // cos(3*pi/16)/2
#define H4 0.35355339059327376f  // cos(4*pi/16)/2
#define H5 0.27778511650980111f  // cos(5*pi/16)/2
#define H6 0.19134171618254489f  // cos(6*pi/16)/2
#define H7 0.09754516100806413f  // cos(7*pi/16)/2

#define NROWS 2048   // 16 images * 128 block-rows
#define GRID  296    // 2 CTAs/SM * 148 SMs

__constant__ float c_qtab[64] = {
    16.f, 11.f, 10.f, 16.f, 24.f, 40.f, 51.f, 61.f,
    12.f, 12.f, 14.f, 19.f, 26.f, 58.f, 60.f, 55.f,
    14.f, 13.f, 16.f, 24.f, 40.f, 57.f, 69.f, 56.f,
    14.f, 17.f, 22.f, 29.f, 51.f, 87.f, 80.f, 62.f,
    18.f, 22.f, 37.f, 56.f, 68.f, 109.f, 103.f, 77.f,
    24.f, 36.f, 55.f, 64.f, 81.f, 104.f, 113.f, 92.f,
    49.f, 64.f, 78.f, 87.f, 103.f, 121.f, 120.f, 101.f,
    72.f, 92.f, 95.f, 98.f, 112.f, 100.f, 103.f, 99.f};

__device__ __forceinline__ unsigned long long mk_evict_last_policy() {
    unsigned long long pol;
    asm("createpolicy.fractional.L2::evict_last.b64 %0, 1.0;" : "=l"(pol));
    return pol;
}

__device__ __forceinline__ float4 ldg_hint(const float* __restrict__ p,
                                           unsigned long long pol) {
    float4 v;
    asm("ld.global.nc.L2::cache_hint.v4.f32 {%0,%1,%2,%3}, [%4], %5;"
        : "=f"(v.x), "=f"(v.y), "=f"(v.z), "=f"(v.w) : "l"(p), "l"(pol));
    return v;
}

__device__ __forceinline__ void dct8(float& x0, float& x1, float& x2, float& x3,
                                     float& x4, float& x5, float& x6, float& x7) {
    float e0 = x0 + x7, e1 = x1 + x6, e2 = x2 + x5, e3 = x3 + x4;
    float o0 = x0 - x7, o1 = x1 - x6, o2 = x2 - x5, o3 = x3 - x4;
    float ee0 = e0 + e3, ee1 = e1 + e2;
    float eo0 = e0 - e3, eo1 = e1 - e2;
    x0 = A0 * (ee0 + ee1);
    x4 = H4 * (ee0 - ee1);
    x2 = H2 * eo0 + H6 * eo1;
    x6 = H6 * eo0 - H2 * eo1;
    x1 = H1 * o0 + H3 * o1 + H5 * o2 + H7 * o3;
    x3 = H3 * o0 - H7 * o1 - H1 * o2 - H5 * o3;
    x5 = H5 * o0 - H1 * o1 + H7 * o2 + H3 * o3;
    x7 = H7 * o0 - H5 * o1 + H3 * o2 - H1 * o3;
}

struct Coef {
    float cA0, cA1, cB0, cB1;
    float cC0, cC1, cC2, cC3;
    float cD0, cD1, cD2, cD3;
    float dcfix;
};

__device__ __forceinline__ void load_tile(const float* __restrict__ img,
                                          int row, int wb, int h,
                                          unsigned long long pol,
                                          float x[8][4]) {
    int b = row >> 7;
    int hb = row & 127;
    const float* p = img + ((size_t)b << 20) + (size_t)hb * 8192 + wb * 8 + h * 4;
#pragma unroll
    for (int r = 0; r < 8; r++) {
        float4 v = ldg_hint(p + (size_t)r * 1024, pol);
        x[r][0] = v.x;   // no -128: uniform shift folded into DC fix
        x[r][1] = v.y;
        x[r][2] = v.z;
        x[r][3] = v.w;
    }
}

__device__ __forceinline__ void process_tile(float x[8][4], int row, int wb,
                                             int h, const Coef& cf,
                                             const float* __restrict__ sScale,
                                             float* __restrict__ out) {
    int b = row >> 7;
    int hb = row & 127;

    // Column transform: thread-local, own 4 columns.
#pragma unroll
    for (int c = 0; c < 4; c++) {
        dct8(x[0][c], x[1][c], x[2][c], x[3][c],
             x[4][c], x[5][c], x[6][c], x[7][c]);
    }

    const float* scb = &sScale[b * 64 + 4 * h];
    float* ob = out + ((size_t)b << 20) + hb * 128 + wb + (size_t)(h * 4) * 16384;

#pragma unroll
    for (int k = 0; k < 8; k++) {
        float v0 = x[k][0], v1 = x[k][1], v2 = x[k][2], v3 = x[k][3];
        float p0 = __shfl_xor_sync(0xffffffffu, v0, 1);
        float p1 = __shfl_xor_sync(0xffffffffu, v1, 1);
        float p2 = __shfl_xor_sync(0xffffffffu, v2, 1);
        float p3 = __shfl_xor_sync(0xffffffffu, v3, 1);
        // s_i = e_i (h=0) / e_{3-i} (h=1);  d_i = o_i (h=0) / -o_{3-i} (h=1)
        float s0 = v0 + p3, s1 = v1 + p2, s2 = v2 + p1, s3 = v3 + p0;
        float d0 = v0 - p3, d1 = v1 - p2, d2 = v2 - p1, d3 = v3 - p0;
        float ee0 = s0 + s3, ee1 = s1 + s2;
        float u0 = s0 - s3, u1 = s1 - s2;

        float oA = cf.cA0 * ee0 + cf.cA1 * ee1;                       // l = 4h+0
        if (k == 0) oA -= cf.dcfix;  // -128 input shift affects only (0,0)
        float oB = cf.cB0 * u0 + cf.cB1 * u1;                         // l = 4h+2
        float oC = cf.cC0 * d0 + cf.cC1 * d1 + cf.cC2 * d2 + cf.cC3 * d3;
        float oD = cf.cD0 * d0 + cf.cD1 * d1 + cf.cD2 * d2 + cf.cD3 * d3;

        float4 sc = *(const float4*)&scb[k * 8];
        float* ok = ob + (size_t)(k * 8) * 16384;
        __stcs(ok,                     oA * sc.x);
        __stcs(ok + (size_t)1 * 16384, oC * sc.y);
        __stcs(ok + (size_t)2 * 16384, oB * sc.z);
        __stcs(ok + (size_t)3 * 16384, oD * sc.w);
    }
}

__global__ __launch_bounds__(256, 2) void jpeg_dct_kernel(
    const float* __restrict__ img,
    const float* __restrict__ qf,
    float* __restrict__ out) {
    __shared__ __align__(16) float sScale[16 * 64];

    // Precompute every image's 64 quant scales once.
    for (int i = threadIdx.x; i < 16 * 64; i += 256) {
        int bi = i >> 6;
        float q = qf[bi];
        float factor = (q < 50.0f) ? (5000.0f / q) : (200.0f - 2.0f * q);
        sScale[i] = 100.0f / (c_qtab[i & 63] * factor);
    }
    __syncthreads();

    int wb = threadIdx.x >> 1;
    int h = threadIdx.x & 1;   // half: columns 4h..4h+3
    bool hi = (h != 0);

    Coef cf;
    cf.cA0 = hi ?  H4 :  A0;  cf.cA1 = hi ? -H4 :  A0;   // l0 / l4
    cf.cB0 = hi ? -H6 :  H2;  cf.cB1 = hi ?  H2 :  H6;   // l2 / l6
    cf.cC0 = hi ? -H3 :  H1;  cf.cC1 = hi ? -H7 :  H3;   // l1 / l5
    cf.cC2 = hi ?  H1 :  H5;  cf.cC3 = hi ? -H5 :  H7;
    cf.cD0 = hi ?  H1 :  H3;  cf.cD1 = hi ? -H3 : -H7;   // l3 / l7
    cf.cD2 = hi ?  H5 : -H1;  cf.cD3 = hi ? -H7 : -H5;
    cf.dcfix = hi ? 0.0f : 1024.0f;

    unsigned long long pol = mk_evict_last_policy();

    // Register double-buffered persistent loop: loads for the next tile are
    // issued before the current tile's compute, so each warp always has
    // 8 LDG.128 in flight during compute+store.
    float xA[8][4], xB[8][4];
    int rA = blockIdx.x;
    load_tile(img, rA, wb, h, pol, xA);
    while (rA < NROWS) {
        int rB = rA + GRID;
        if (rB < NROWS) load_tile(img, rB, wb, h, pol, xB);
        process_tile(xA, rA, wb, h, cf, sScale, out);
        rA += 2 * GRID;
        if (rA < NROWS) load_tile(img, rA, wb, h, pol, xA);
        if (rB < NROWS) process_tile(xB, rB, wb, h, cf, sScale, out);
    }
}

extern "C" void kernel_launch(void* const* d_in, const int* in_sizes, int n_in,
                              void* d_out, int out_size) {
    const float* img = (const float*)d_in[0];
    const float* qf = (const float*)d_in[1];
    float* out = (float*)d_out;
    jpeg_dct_kernel<<<GRID, 256>>>(img, qf, out);
}